// round 7
// baseline (speedup 1.0000x reference)
#include <cuda_runtime.h>
#include <math.h>
#include <stdint.h>

// ---------------- problem constants ----------------
#define D_   1024
#define H_   8
#define E_   128
#define B_   4
#define S_   2048
#define NT_  (B_ * S_)
#define EPS_ 1e-6f

// ---------------- device scratch ----------------
__device__ float g_mod [NT_ * D_];
__device__ float g_h   [NT_ * D_];
__device__ float g_q   [NT_ * D_];
__device__ float g_k   [NT_ * D_];
__device__ float g_v   [NT_ * D_];
__device__ float g_mod2[NT_ * D_];
__device__ float g_h2  [NT_ * D_];

__device__ __forceinline__ float elu1(float x) { return x > 0.f ? x : expm1f(x); }

__device__ __forceinline__ uint32_t tf32_of(float f) {
  uint32_t u;
  asm("cvt.rna.tf32.f32 %0, %1;" : "=r"(u) : "f"(f));
  return u;
}
__device__ __forceinline__ float4 tf32x4(float4 v) {
  return make_float4(__uint_as_float(tf32_of(v.x)), __uint_as_float(tf32_of(v.y)),
                     __uint_as_float(tf32_of(v.z)), __uint_as_float(tf32_of(v.w)));
}

__device__ __forceinline__ void mma_tf32(float* d, const uint32_t* a, const uint32_t* b) {
  asm volatile(
      "mma.sync.aligned.m16n8k8.row.col.f32.tf32.tf32.f32 "
      "{%0,%1,%2,%3}, {%4,%5,%6,%7}, {%8,%9}, {%0,%1,%2,%3};"
      : "+f"(d[0]), "+f"(d[1]), "+f"(d[2]), "+f"(d[3])
      : "r"(a[0]), "r"(a[1]), "r"(a[2]), "r"(a[3]), "r"(b[0]), "r"(b[1]));
}

__device__ __forceinline__ void ldsm_x4(uint32_t* r, uint32_t saddr) {
  asm volatile("ldmatrix.sync.aligned.m8n8.x4.shared.b16 {%0,%1,%2,%3}, [%4];"
               : "=r"(r[0]), "=r"(r[1]), "=r"(r[2]), "=r"(r[3]) : "r"(saddr));
}

__device__ __forceinline__ uint32_t smem_u32(const void* p) {
  return (uint32_t)__cvta_generic_to_shared(p);
}

// ============================================================
// TF32 tensor-core GEMM (convert at fill, ldmatrix A-fragments).
// 128x128 block tile, K-tile 32, 8 warps (2x4), warp tile 64x32.
// ============================================================
#define GBM 128
#define GBN 128
#define GBK 32
#define LDA_S 36
#define LDB_S 136

template <bool FFN>
__device__ __forceinline__ void gemm_tf32_core(
    const float* __restrict__ A, int lda,
    const float* __restrict__ Bm, int ldb,
    float* __restrict__ C, int ldc, int K,
    const float* __restrict__ bias, const float* __restrict__ resid) {
  __shared__ float As[GBM * LDA_S];
  __shared__ float Bs[GBK * LDB_S];

  const int t = threadIdx.x;
  const int lane = t & 31, wid = t >> 5;
  const int g = lane >> 2, tg = lane & 3;
  const int wr = wid >> 2, wc = wid & 3;

  const int a_r = t >> 3;        // 0..31
  const int a_c = (t & 7) * 4;   // 0..28
  const int b_r = t >> 5;        // 0..7
  const int b_c = (t & 31) * 4;  // 0..124

  // per-thread ldmatrix base addresses for A fragments
  uint32_t aa[4];
  {
    uint32_t as_u = smem_u32(As);
#pragma unroll
    for (int i = 0; i < 4; i++)
      aa[i] = as_u + 4 * ((wr * 64 + i * 16 + (lane & 15)) * LDA_S + (lane >> 4) * 4);
  }

  float acc[4][4][4];
#pragma unroll
  for (int i = 0; i < 4; i++)
#pragma unroll
    for (int j = 0; j < 4; j++)
#pragma unroll
      for (int r = 0; r < 4; r++) acc[i][j][r] = 0.f;

  for (int k0 = 0; k0 < K; k0 += GBK) {
#pragma unroll
    for (int i = 0; i < 4; i++) {
      int r = a_r + i * 32;
      float4 v = *(const float4*)(A + (size_t)r * lda + k0 + a_c);
      *(float4*)&As[r * LDA_S + a_c] = tf32x4(v);
    }
#pragma unroll
    for (int i = 0; i < 4; i++) {
      int r = b_r + i * 8;
      float4 v = *(const float4*)(Bm + (size_t)(k0 + r) * ldb + b_c);
      *(float4*)&Bs[r * LDB_S + b_c] = tf32x4(v);
    }
    __syncthreads();

    const uint32_t* bsu = (const uint32_t*)Bs;
#pragma unroll
    for (int kk = 0; kk < GBK; kk += 8) {
      uint32_t af[4][4], bf[4][2];
#pragma unroll
      for (int i = 0; i < 4; i++) ldsm_x4(af[i], aa[i] + 4 * kk);
#pragma unroll
      for (int j = 0; j < 4; j++) {
        int c0 = wc * 32 + j * 8;
        bf[j][0] = bsu[(kk + tg) * LDB_S + c0 + g];
        bf[j][1] = bsu[(kk + tg + 4) * LDB_S + c0 + g];
      }
#pragma unroll
      for (int i = 0; i < 4; i++)
#pragma unroll
        for (int j = 0; j < 4; j++) mma_tf32(acc[i][j], af[i], bf[j]);
    }
    __syncthreads();
  }

  // epilogue
#pragma unroll
  for (int i = 0; i < 4; i++) {
    int rA = wr * 64 + i * 16 + g;
    int rB = rA + 8;
#pragma unroll
    for (int j = 0; j < 4; j++) {
      int c = wc * 32 + j * 8 + 2 * tg;
      float2 o0 = make_float2(acc[i][j][0], acc[i][j][1]);
      float2 o1 = make_float2(acc[i][j][2], acc[i][j][3]);
      if (FFN) {
        float2 bv = *(const float2*)(bias + c);
        float2 r0 = *(const float2*)(resid + (size_t)rA * ldc + c);
        float2 r1 = *(const float2*)(resid + (size_t)rB * ldc + c);
        o0.x = r0.x + elu1(o0.x + bv.x);
        o0.y = r0.y + elu1(o0.y + bv.y);
        o1.x = r1.x + elu1(o1.x + bv.x);
        o1.y = r1.y + elu1(o1.y + bv.y);
      }
      *(float2*)(C + (size_t)rA * ldc + c) = o0;
      *(float2*)(C + (size_t)rB * ldc + c) = o1;
    }
  }
}

__global__ void __launch_bounds__(256, 2) k_gemm_dense(const float* __restrict__ A,
                                                       const float* __restrict__ W,
                                                       float* __restrict__ C) {
  const size_t moff = (size_t)blockIdx.y * GBM * D_;
  gemm_tf32_core<false>(A + moff, D_, W + blockIdx.x * GBN, D_,
                        C + moff + blockIdx.x * GBN, D_, D_, nullptr, nullptr);
}

__global__ void __launch_bounds__(256, 2) k_gemm_ffn(const float* __restrict__ A,
                                                     const float* __restrict__ W,
                                                     const float* __restrict__ bias,
                                                     const float* __restrict__ resid,
                                                     float* __restrict__ C) {
  const size_t moff = (size_t)blockIdx.y * GBM * D_;
  const size_t off = moff + blockIdx.x * GBN;
  gemm_tf32_core<true>(A + moff, D_, W + blockIdx.x * GBN, D_, C + off, D_, D_,
                       bias + blockIdx.x * GBN, resid + off);
}

__global__ void __launch_bounds__(256, 2) k_gemm_qkv(const float* __restrict__ Hm,
                                                     const float* __restrict__ Wq,
                                                     const float* __restrict__ Wk,
                                                     const float* __restrict__ Wv,
                                                     float* __restrict__ Oq,
                                                     float* __restrict__ Ok,
                                                     float* __restrict__ Ov) {
  const int which = blockIdx.z;
  const float* W = which == 0 ? Wq : (which == 1 ? Wk : Wv);
  float* Out = which == 0 ? Oq : (which == 1 ? Ok : Ov);
  const int bh = blockIdx.y;
  const int b = bh >> 3, h = bh & 7;
  const float* A = Hm + ((size_t)b * S_ + (size_t)blockIdx.x * GBM) * D_ + h * E_;
  const float* Wp = W + h * E_ * E_;
  float* C = Out + ((size_t)bh * S_ + (size_t)blockIdx.x * GBM) * E_;
  gemm_tf32_core<false>(A, D_, Wp, E_, C, E_, E_, nullptr, nullptr);
}

// ============================================================
// LayerNorm over last dim (1024), one block per row
// ============================================================
__global__ void __launch_bounds__(256) k_ln(const float* __restrict__ in,
                                            float* __restrict__ out,
                                            const float* __restrict__ gamma,
                                            const float* __restrict__ beta) {
  const size_t row = blockIdx.x;
  const int t = threadIdx.x;
  float4 v = ((const float4*)(in + row * D_))[t];
  float s  = v.x + v.y + v.z + v.w;
  float s2 = v.x * v.x + v.y * v.y + v.z * v.z + v.w * v.w;
#pragma unroll
  for (int off = 16; off; off >>= 1) {
    s  += __shfl_xor_sync(0xffffffffu, s, off);
    s2 += __shfl_xor_sync(0xffffffffu, s2, off);
  }
  __shared__ float sb[16];
  if ((t & 31) == 0) { sb[t >> 5] = s; sb[(t >> 5) + 8] = s2; }
  __syncthreads();
  float tot = 0.f, tot2 = 0.f;
#pragma unroll
  for (int i = 0; i < 8; i++) { tot += sb[i]; tot2 += sb[i + 8]; }
  const float mean = tot * (1.f / D_);
  const float var  = tot2 * (1.f / D_) - mean * mean;
  const float inv  = rsqrtf(var + EPS_);
  float4 gm = ((const float4*)gamma)[t];
  float4 bb = ((const float4*)beta)[t];
  float4 o;
  o.x = (v.x - mean) * inv * gm.x + bb.x;
  o.y = (v.y - mean) * inv * gm.y + bb.y;
  o.z = (v.z - mean) * inv * gm.z + bb.z;
  o.w = (v.w - mean) * inv * gm.w + bb.w;
  ((float4*)(out + row * D_))[t] = o;
}

// ============================================================
// Flash attention: KT=64, convert-at-fill tf32, ldmatrix frags,
// parallel softmax, fused residual. 8 warps (2 x 4).
// ============================================================
#define QT 64
#define KTT 64
#define NKT (S_ / KTT)
#define LQ 132
#define LK 132
#define LV 136
#define LP 68
#define ATTN_SMEM ((64 * LQ + KTT * LK + KTT * LV + 64 * LP + 192) * 4)

__global__ void __launch_bounds__(256) k_attn(const float* __restrict__ Qg,
                                              const float* __restrict__ Kg,
                                              const float* __restrict__ Vg,
                                              const float* __restrict__ modin,
                                              float* __restrict__ modout) {
  extern __shared__ float sm[];
  float* q_s = sm;                          // [64][LQ]
  float* k_s = q_s + 64 * LQ;               // [KTT][LK]
  float* v_s = k_s + KTT * LK;              // [KTT][LV]
  float* p_s = v_s + KTT * LV;              // [64][LP]
  float* alpha_s = p_s + 64 * LP;           // [64]
  float* l_s = alpha_s + 64;                // [64]
  float* m_s = alpha_s + 128;               // [64]

  const int t = threadIdx.x;
  const int lane = t & 31, wid = t >> 5;
  const int g = lane >> 2, tg = lane & 3;
  const int wr = wid >> 2, wc = wid & 3;

  const int q0 = blockIdx.x * QT;
  const int h = blockIdx.y, b = blockIdx.z;
  const size_t bh = (size_t)b * H_ + h;

  const float* Kp = Kg + bh * S_ * E_;
  const float* Vp = Vg + bh * S_ * E_;

  const int ldrow = t >> 5, ldcol = (t & 31) * 4;

  // ldmatrix base addresses
  uint32_t qa[2], pa[2], ka;
  {
    uint32_t qu = smem_u32(q_s), pu = smem_u32(p_s), ku = smem_u32(k_s);
    const int lrow = lane & 15, lkw = (lane >> 4) * 4;
#pragma unroll
    for (int i = 0; i < 2; i++) {
      qa[i] = qu + 4 * ((wr * 32 + i * 16 + lrow) * LQ + lkw);
      pa[i] = pu + 4 * ((wr * 32 + i * 16 + lrow) * LP + lkw);
    }
    ka = ku + 4 * ((wc * 16 + lrow) * LK + lkw);
  }

  // load + convert Q tile once
  {
    const float* Qp = Qg + (bh * S_ + q0) * E_;
#pragma unroll
    for (int i = 0; i < 8; i++) {
      int r = ldrow + i * 8;
      float4 v = *(const float4*)(Qp + (size_t)r * E_ + ldcol);
      *(float4*)&q_s[r * LQ + ldcol] = tf32x4(v);
    }
  }

  if (t < 64) { m_s[t] = -1e30f; l_s[t] = 0.f; }

  float o[2][4][4];
#pragma unroll
  for (int i = 0; i < 2; i++)
#pragma unroll
    for (int j = 0; j < 4; j++)
#pragma unroll
      for (int r = 0; r < 4; r++) o[i][j][r] = 0.f;

  for (int kt = 0; kt < NKT; kt++) {
    if (kt) __syncthreads();    // protect K/V/p_s reuse
    {
      const float* kb = Kp + (size_t)kt * KTT * E_;
      const float* vb = Vp + (size_t)kt * KTT * E_;
#pragma unroll
      for (int i = 0; i < 8; i++) {
        int r = ldrow + i * 8;
        float4 kv = *(const float4*)(kb + (size_t)r * E_ + ldcol);
        float4 vv = *(const float4*)(vb + (size_t)r * E_ + ldcol);
        *(float4*)&k_s[r * LK + ldcol] = tf32x4(kv);
        *(float4*)&v_s[r * LV + ldcol] = tf32x4(vv);
      }
    }
    __syncthreads();

    // ---- phase A: scores = Q K^T (64x64), warp tile 32x16 ----
    float sc[2][2][4];
#pragma unroll
    for (int i = 0; i < 2; i++)
#pragma unroll
      for (int j = 0; j < 2; j++)
#pragma unroll
        for (int r = 0; r < 4; r++) sc[i][j][r] = 0.f;

#pragma unroll
    for (int kk = 0; kk < E_; kk += 8) {
      uint32_t af[2][4], bfk[4];
      ldsm_x4(af[0], qa[0] + 4 * kk);
      ldsm_x4(af[1], qa[1] + 4 * kk);
      ldsm_x4(bfk, ka + 4 * kk);   // [j0k0, j1k0, j0k4, j1k4]
      uint32_t b0[2] = {bfk[0], bfk[2]};
      uint32_t b1[2] = {bfk[1], bfk[3]};
#pragma unroll
      for (int i = 0; i < 2; i++) {
        mma_tf32(sc[i][0], af[i], b0);
        mma_tf32(sc[i][1], af[i], b1);
      }
    }

    // scatter raw scores to p_s
#pragma unroll
    for (int i = 0; i < 2; i++) {
      int rA = wr * 32 + i * 16 + g;
#pragma unroll
      for (int j = 0; j < 2; j++) {
        int c = wc * 16 + j * 8 + 2 * tg;
        *(float2*)&p_s[rA * LP + c] = make_float2(sc[i][j][0], sc[i][j][1]);
        *(float2*)&p_s[(rA + 8) * LP + c] = make_float2(sc[i][j][2], sc[i][j][3]);
      }
    }
    __syncthreads();

    // ---- online softmax: 4 threads per row, writes tf32 P ----
    {
      const int row = t >> 2, part = t & 3;
      float4* pr = (float4*)&p_s[row * LP + part * 16];
      float4 v0 = pr[0], v1 = pr[1], v2 = pr[2], v3 = pr[3];
      float mt = fmaxf(fmaxf(fmaxf(v0.x, v0.y), fmaxf(v0.z, v0.w)),
                       fmaxf(fmaxf(v1.x, v1.y), fmaxf(v1.z, v1.w)));
      mt = fmaxf(mt, fmaxf(fmaxf(fmaxf(v2.x, v2.y), fmaxf(v2.z, v2.w)),
                           fmaxf(fmaxf(v3.x, v3.y), fmaxf(v3.z, v3.w))));
      mt = fmaxf(mt, __shfl_xor_sync(0xffffffffu, mt, 1));
      mt = fmaxf(mt, __shfl_xor_sync(0xffffffffu, mt, 2));
      float m_old = m_s[row];
      float mn = fmaxf(m_old, mt);
      v0.x = __expf(v0.x - mn); v0.y = __expf(v0.y - mn);
      v0.z = __expf(v0.z - mn); v0.w = __expf(v0.w - mn);
      v1.x = __expf(v1.x - mn); v1.y = __expf(v1.y - mn);
      v1.z = __expf(v1.z - mn); v1.w = __expf(v1.w - mn);
      v2.x = __expf(v2.x - mn); v2.y = __expf(v2.y - mn);
      v2.z = __expf(v2.z - mn); v2.w = __expf(v2.w - mn);
      v3.x = __expf(v3.x - mn); v3.y = __expf(v3.y - mn);
      v3.z = __expf(v3.z - mn); v3.w = __expf(v3.w - mn);
      float s = (v0.x + v0.y + v0.z + v0.w) + (v1.x + v1.y + v1.z + v1.w) +
                (v2.x + v2.y + v2.z + v2.w) + (v3.x + v3.y + v3.z + v3.w);
      s += __shfl_xor_sync(0xffffffffu, s, 1);
      s += __shfl_xor_sync(0xffffffffu, s, 2);
      pr[0] = tf32x4(v0); pr[1] = tf32x4(v1);
      pr[2] = tf32x4(v2); pr[3] = tf32x4(v3);
      __syncwarp();
      if (part == 0) {
        float alpha = __expf(m_old - mn);
        m_s[row] = mn;
        alpha_s[row] = alpha;
        l_s[row] = l_s[row] * alpha + s;
      }
    }
    __syncthreads();

    // ---- rescale O ----
#pragma unroll
    for (int i = 0; i < 2; i++) {
      int rA = wr * 32 + i * 16 + g;
      float aA = alpha_s[rA], aB = alpha_s[rA + 8];
#pragma unroll
      for (int j = 0; j < 4; j++) {
        o[i][j][0] *= aA; o[i][j][1] *= aA;
        o[i][j][2] *= aB; o[i][j][3] *= aB;
      }
    }

    // ---- phase B: O += P V (64x128), warp tile 32x32 ----
    const uint32_t* vsu = (const uint32_t*)v_s;
#pragma unroll
    for (int kk = 0; kk < KTT; kk += 8) {
      uint32_t af[2][4], bf[4][2];
      ldsm_x4(af[0], pa[0] + 4 * kk);
      ldsm_x4(af[1], pa[1] + 4 * kk);
#pragma unroll
      for (int j = 0; j < 4; j++) {
        int cb = wc * 32 + j * 8;
        bf[j][0] = vsu[(kk + tg) * LV + cb + g];
        bf[j][1] = vsu[(kk + tg + 4) * LV + cb + g];
      }
#pragma unroll
      for (int i = 0; i < 2; i++)
#pragma unroll
        for (int j = 0; j < 4; j++) mma_tf32(o[i][j], af[i], bf[j]);
    }
  }

  // ---- epilogue: normalize + residual ----
#pragma unroll
  for (int i = 0; i < 2; i++) {
    int rA = wr * 32 + i * 16 + g;
    int rB = rA + 8;
    float invA = 1.f / l_s[rA];
    float invB = 1.f / l_s[rB];
#pragma unroll
    for (int j = 0; j < 4; j++) {
      int c = wc * 32 + j * 8 + 2 * tg;
      size_t baseA = ((size_t)b * S_ + q0 + rA) * D_ + (size_t)h * E_ + c;
      size_t baseB = ((size_t)b * S_ + q0 + rB) * D_ + (size_t)h * E_ + c;
      float2 mA = *(const float2*)(modin + baseA);
      float2 mB = *(const float2*)(modin + baseB);
      float2 oA = make_float2(mA.x + o[i][j][0] * invA, mA.y + o[i][j][1] * invA);
      float2 oB = make_float2(mB.x + o[i][j][2] * invB, mB.y + o[i][j][3] * invB);
      *(float2*)(modout + baseA) = oA;
      *(float2*)(modout + baseB) = oB;
    }
  }
}

// ============================================================
extern "C" void kernel_launch(void* const* d_in, const int* in_sizes, int n_in,
                              void* d_out, int out_size) {
  const float* x     = (const float*)d_in[0];
  const float* W_in  = (const float*)d_in[1];
  const float* gamma = (const float*)d_in[2];
  const float* beta  = (const float*)d_in[3];
  const float* Wq    = (const float*)d_in[4];
  const float* Wk    = (const float*)d_in[5];
  const float* Wv    = (const float*)d_in[6];
  const float* Wf    = (const float*)d_in[7];
  const float* bf    = (const float*)d_in[8];
  float* out = (float*)d_out;

  float *mod, *h, *q, *k, *v, *mod2, *h2;
  cudaGetSymbolAddress((void**)&mod,  g_mod);
  cudaGetSymbolAddress((void**)&h,    g_h);
  cudaGetSymbolAddress((void**)&q,    g_q);
  cudaGetSymbolAddress((void**)&k,    g_k);
  cudaGetSymbolAddress((void**)&v,    g_v);
  cudaGetSymbolAddress((void**)&mod2, g_mod2);
  cudaGetSymbolAddress((void**)&h2,   g_h2);

  cudaFuncSetAttribute(k_attn, cudaFuncAttributeMaxDynamicSharedMemorySize, ATTN_SMEM);

  dim3 gdense(D_ / GBN, NT_ / GBM);     // (8, 64)
  k_gemm_dense<<<gdense, 256>>>(x, W_in, mod);

  k_ln<<<NT_, 256>>>(mod, h, gamma, beta);

  dim3 gqkv(S_ / GBM, B_ * H_, 3);      // (16, 32, 3)
  k_gemm_qkv<<<gqkv, 256>>>(h, Wq, Wk, Wv, q, k, v);

  dim3 gattn(S_ / QT, H_, B_);          // (32, 8, 4)
  k_attn<<<gattn, 256, ATTN_SMEM>>>(q, k, v, mod, mod2);

  k_ln<<<NT_, 256>>>(mod2, h2, gamma, beta);

  k_gemm_ffn<<<gdense, 256>>>(h2, Wf, bf, mod2, out);
}

// round 8
// speedup vs baseline: 1.2345x; 1.2345x over previous
#include <cuda_runtime.h>
#include <math.h>
#include <stdint.h>

// ---------------- problem constants ----------------
#define D_   1024
#define H_   8
#define E_   128
#define B_   4
#define S_   2048
#define NT_  (B_ * S_)
#define EPS_ 1e-6f

// ---------------- device scratch ----------------
__device__ float g_mod [NT_ * D_];
__device__ float g_h   [NT_ * D_];
__device__ float g_q   [NT_ * D_];
__device__ float g_k   [NT_ * D_];
__device__ float g_v   [NT_ * D_];
__device__ float g_mod2[NT_ * D_];
__device__ float g_h2  [NT_ * D_];

__device__ __forceinline__ float elu1(float x) { return x > 0.f ? x : expm1f(x); }

__device__ __forceinline__ float f2tf(float f) {
  uint32_t u;
  asm("cvt.rna.tf32.f32 %0, %1;" : "=r"(u) : "f"(f));
  return __uint_as_float(u);
}
__device__ __forceinline__ float4 tf32x4(float4 v) {
  return make_float4(f2tf(v.x), f2tf(v.y), f2tf(v.z), f2tf(v.w));
}

__device__ __forceinline__ void mma_tf32(float* d, const uint32_t* a, const uint32_t* b) {
  asm volatile(
      "mma.sync.aligned.m16n8k8.row.col.f32.tf32.tf32.f32 "
      "{%0,%1,%2,%3}, {%4,%5,%6,%7}, {%8,%9}, {%0,%1,%2,%3};"
      : "+f"(d[0]), "+f"(d[1]), "+f"(d[2]), "+f"(d[3])
      : "r"(a[0]), "r"(a[1]), "r"(a[2]), "r"(a[3]), "r"(b[0]), "r"(b[1]));
}

// ============================================================
// TF32 tensor-core GEMM (R2 core): 128x128 block tile, K-tile 32.
// 256 threads = 8 warps (2 x 4), warp tile 64x32.
// ============================================================
#define GBM 128
#define GBN 128
#define GBK 32
#define LDA_S 36
#define LDB_S 136

template <bool FFN>
__device__ __forceinline__ void gemm_tf32_core(
    const float* __restrict__ A, int lda,
    const float* __restrict__ Bm, int ldb,
    float* __restrict__ C, int ldc, int K,
    const float* __restrict__ bias, const float* __restrict__ resid) {
  __shared__ float As[GBM * LDA_S];
  __shared__ float Bs[GBK * LDB_S];

  const int t = threadIdx.x;
  const int lane = t & 31, wid = t >> 5;
  const int g = lane >> 2, tg = lane & 3;
  const int wr = wid >> 2, wc = wid & 3;

  const int a_c = (t & 7) * 4;   // 0..28
  const int a_r = t >> 3;        // 0..31
  const int b_c = (t & 31) * 4;  // 0..124
  const int b_r = t >> 5;        // 0..7

  float acc[4][4][4];
#pragma unroll
  for (int i = 0; i < 4; i++)
#pragma unroll
    for (int j = 0; j < 4; j++)
#pragma unroll
      for (int r = 0; r < 4; r++) acc[i][j][r] = 0.f;

  for (int k0 = 0; k0 < K; k0 += GBK) {
#pragma unroll
    for (int i = 0; i < 4; i++) {
      int r = a_r + i * 32;
      float4 v = *(const float4*)(A + (size_t)r * lda + k0 + a_c);
      *(float4*)&As[r * LDA_S + a_c] = tf32x4(v);
    }
#pragma unroll
    for (int i = 0; i < 4; i++) {
      int r = b_r + i * 8;
      float4 v = *(const float4*)(Bm + (size_t)(k0 + r) * ldb + b_c);
      *(float4*)&Bs[r * LDB_S + b_c] = tf32x4(v);
    }
    __syncthreads();

    const uint32_t* as = (const uint32_t*)As;
    const uint32_t* bs = (const uint32_t*)Bs;
#pragma unroll
    for (int kk = 0; kk < GBK; kk += 8) {
      uint32_t af[4][4], bf[4][2];
#pragma unroll
      for (int i = 0; i < 4; i++) {
        int r0 = wr * 64 + i * 16;
        af[i][0] = as[(r0 + g) * LDA_S + kk + tg];
        af[i][1] = as[(r0 + g + 8) * LDA_S + kk + tg];
        af[i][2] = as[(r0 + g) * LDA_S + kk + tg + 4];
        af[i][3] = as[(r0 + g + 8) * LDA_S + kk + tg + 4];
      }
#pragma unroll
      for (int j = 0; j < 4; j++) {
        int c0 = wc * 32 + j * 8;
        bf[j][0] = bs[(kk + tg) * LDB_S + c0 + g];
        bf[j][1] = bs[(kk + tg + 4) * LDB_S + c0 + g];
      }
#pragma unroll
      for (int i = 0; i < 4; i++)
#pragma unroll
        for (int j = 0; j < 4; j++) mma_tf32(acc[i][j], af[i], bf[j]);
    }
    __syncthreads();
  }

  // epilogue
#pragma unroll
  for (int i = 0; i < 4; i++) {
    int rA = wr * 64 + i * 16 + g;
    int rB = rA + 8;
#pragma unroll
    for (int j = 0; j < 4; j++) {
      int c = wc * 32 + j * 8 + 2 * tg;
      float2 o0 = make_float2(acc[i][j][0], acc[i][j][1]);
      float2 o1 = make_float2(acc[i][j][2], acc[i][j][3]);
      if (FFN) {
        float2 bv = *(const float2*)(bias + c);
        float2 r0 = *(const float2*)(resid + (size_t)rA * ldc + c);
        float2 r1 = *(const float2*)(resid + (size_t)rB * ldc + c);
        o0.x = r0.x + elu1(o0.x + bv.x);
        o0.y = r0.y + elu1(o0.y + bv.y);
        o1.x = r1.x + elu1(o1.x + bv.x);
        o1.y = r1.y + elu1(o1.y + bv.y);
      }
      *(float2*)(C + (size_t)rA * ldc + c) = o0;
      *(float2*)(C + (size_t)rB * ldc + c) = o1;
    }
  }
}

__global__ void __launch_bounds__(256) k_gemm_dense(const float* __restrict__ A,
                                                    const float* __restrict__ W,
                                                    float* __restrict__ C) {
  const size_t moff = (size_t)blockIdx.y * GBM * D_;
  gemm_tf32_core<false>(A + moff, D_, W + blockIdx.x * GBN, D_,
                        C + moff + blockIdx.x * GBN, D_, D_, nullptr, nullptr);
}

__global__ void __launch_bounds__(256) k_gemm_ffn(const float* __restrict__ A,
                                                  const float* __restrict__ W,
                                                  const float* __restrict__ bias,
                                                  const float* __restrict__ resid,
                                                  float* __restrict__ C) {
  const size_t moff = (size_t)blockIdx.y * GBM * D_;
  const size_t off = moff + blockIdx.x * GBN;
  gemm_tf32_core<true>(A + moff, D_, W + blockIdx.x * GBN, D_, C + off, D_, D_,
                       bias + blockIdx.x * GBN, resid + off);
}

__global__ void __launch_bounds__(256) k_gemm_qkv(const float* __restrict__ Hm,
                                                  const float* __restrict__ Wq,
                                                  const float* __restrict__ Wk,
                                                  const float* __restrict__ Wv,
                                                  float* __restrict__ Oq,
                                                  float* __restrict__ Ok,
                                                  float* __restrict__ Ov) {
  const int which = blockIdx.z;
  const float* W = which == 0 ? Wq : (which == 1 ? Wk : Wv);
  float* Out = which == 0 ? Oq : (which == 1 ? Ok : Ov);
  const int bh = blockIdx.y;
  const int b = bh >> 3, h = bh & 7;
  const float* A = Hm + ((size_t)b * S_ + (size_t)blockIdx.x * GBM) * D_ + h * E_;
  const float* Wp = W + h * E_ * E_;
  float* C = Out + ((size_t)bh * S_ + (size_t)blockIdx.x * GBM) * E_;
  gemm_tf32_core<false>(A, D_, Wp, E_, C, E_, E_, nullptr, nullptr);
}

// ============================================================
// LayerNorm over last dim (1024), one block per row
// ============================================================
__global__ void __launch_bounds__(256) k_ln(const float* __restrict__ in,
                                            float* __restrict__ out,
                                            const float* __restrict__ gamma,
                                            const float* __restrict__ beta) {
  const size_t row = blockIdx.x;
  const int t = threadIdx.x;
  float4 v = ((const float4*)(in + row * D_))[t];
  float s  = v.x + v.y + v.z + v.w;
  float s2 = v.x * v.x + v.y * v.y + v.z * v.z + v.w * v.w;
#pragma unroll
  for (int off = 16; off; off >>= 1) {
    s  += __shfl_xor_sync(0xffffffffu, s, off);
    s2 += __shfl_xor_sync(0xffffffffu, s2, off);
  }
  __shared__ float sb[16];
  if ((t & 31) == 0) { sb[t >> 5] = s; sb[(t >> 5) + 8] = s2; }
  __syncthreads();
  float tot = 0.f, tot2 = 0.f;
#pragma unroll
  for (int i = 0; i < 8; i++) { tot += sb[i]; tot2 += sb[i + 8]; }
  const float mean = tot * (1.f / D_);
  const float var  = tot2 * (1.f / D_) - mean * mean;
  const float inv  = rsqrtf(var + EPS_);
  float4 gm = ((const float4*)gamma)[t];
  float4 bb = ((const float4*)beta)[t];
  float4 o;
  o.x = (v.x - mean) * inv * gm.x + bb.x;
  o.y = (v.y - mean) * inv * gm.y + bb.y;
  o.z = (v.z - mean) * inv * gm.z + bb.z;
  o.w = (v.w - mean) * inv * gm.w + bb.w;
  ((float4*)(out + row * D_))[t] = o;
}

// ============================================================
// Flash attention, QT=128, KT=64, tf32 tensor cores (R2 style:
// convert at smem fill), parallel softmax, fused residual.
// 8 warps arranged 4 x 2.
// Phase A (scores 128x64): warp tile 32x32.
// Phase B (O += P V, 128x128): warp tile 32x64.
// ============================================================
#define QT 128
#define KTT 64
#define NKT (S_ / KTT)
#define LQ 132
#define LK 132
#define LV 136
#define LP 68
#define ATTN_SMEM ((QT * LQ + KTT * LK + KTT * LV + QT * LP + 3 * QT) * 4)

__global__ void __launch_bounds__(256) k_attn(const float* __restrict__ Qg,
                                              const float* __restrict__ Kg,
                                              const float* __restrict__ Vg,
                                              const float* __restrict__ modin,
                                              float* __restrict__ modout) {
  extern __shared__ float sm[];
  float* q_s = sm;                          // [QT][LQ]
  float* k_s = q_s + QT * LQ;               // [KTT][LK]
  float* v_s = k_s + KTT * LK;              // [KTT][LV]
  float* p_s = v_s + KTT * LV;              // [QT][LP]
  float* alpha_s = p_s + QT * LP;           // [QT]
  float* l_s = alpha_s + QT;                // [QT]
  float* m_s = alpha_s + 2 * QT;            // [QT]

  const int t = threadIdx.x;
  const int lane = t & 31, wid = t >> 5;
  const int g = lane >> 2, tg = lane & 3;
  const int wr = wid >> 1, wc = wid & 1;    // 4 x 2 warp grid

  const int q0 = blockIdx.x * QT;
  const int h = blockIdx.y, b = blockIdx.z;
  const size_t bh = (size_t)b * H_ + h;

  const float* Kp = Kg + bh * S_ * E_;
  const float* Vp = Vg + bh * S_ * E_;

  const int ldrow = t >> 5, ldcol = (t & 31) * 4;

  // load + convert Q tile once (128 rows)
  {
    const float* Qp = Qg + (bh * S_ + q0) * E_;
#pragma unroll
    for (int i = 0; i < 16; i++) {
      int r = ldrow + i * 8;
      float4 v = *(const float4*)(Qp + (size_t)r * E_ + ldcol);
      *(float4*)&q_s[r * LQ + ldcol] = tf32x4(v);
    }
  }

  if (t < QT) { m_s[t] = -1e30f; l_s[t] = 0.f; }

  float o[2][8][4];
#pragma unroll
  for (int i = 0; i < 2; i++)
#pragma unroll
    for (int j = 0; j < 8; j++)
#pragma unroll
      for (int r = 0; r < 4; r++) o[i][j][r] = 0.f;

  for (int kt = 0; kt < NKT; kt++) {
    if (kt) __syncthreads();    // protect K/V/p_s reuse
    {
      const float* kb = Kp + (size_t)kt * KTT * E_;
      const float* vb = Vp + (size_t)kt * KTT * E_;
#pragma unroll
      for (int i = 0; i < 8; i++) {
        int r = ldrow + i * 8;
        float4 kv = *(const float4*)(kb + (size_t)r * E_ + ldcol);
        float4 vv = *(const float4*)(vb + (size_t)r * E_ + ldcol);
        *(float4*)&k_s[r * LK + ldcol] = tf32x4(kv);
        *(float4*)&v_s[r * LV + ldcol] = tf32x4(vv);
      }
    }
    __syncthreads();

    // ---- phase A: scores = Q K^T (128x64), warp tile 32x32 ----
    float sc[2][4][4];
#pragma unroll
    for (int i = 0; i < 2; i++)
#pragma unroll
      for (int j = 0; j < 4; j++)
#pragma unroll
        for (int r = 0; r < 4; r++) sc[i][j][r] = 0.f;

    const uint32_t* qs = (const uint32_t*)q_s;
    const uint32_t* ks = (const uint32_t*)k_s;
#pragma unroll
    for (int kk = 0; kk < E_; kk += 8) {
      uint32_t af[2][4], bf[4][2];
#pragma unroll
      for (int i = 0; i < 2; i++) {
        int r0 = wr * 32 + i * 16;
        af[i][0] = qs[(r0 + g) * LQ + kk + tg];
        af[i][1] = qs[(r0 + g + 8) * LQ + kk + tg];
        af[i][2] = qs[(r0 + g) * LQ + kk + tg + 4];
        af[i][3] = qs[(r0 + g + 8) * LQ + kk + tg + 4];
      }
#pragma unroll
      for (int j = 0; j < 4; j++) {
        int c0 = wc * 32 + j * 8;
        bf[j][0] = ks[(c0 + g) * LK + kk + tg];
        bf[j][1] = ks[(c0 + g) * LK + kk + tg + 4];
      }
#pragma unroll
      for (int i = 0; i < 2; i++)
#pragma unroll
        for (int j = 0; j < 4; j++) mma_tf32(sc[i][j], af[i], bf[j]);
    }

    // scatter raw scores to p_s
#pragma unroll
    for (int i = 0; i < 2; i++) {
      int rA = wr * 32 + i * 16 + g;
#pragma unroll
      for (int j = 0; j < 4; j++) {
        int c = wc * 32 + j * 8 + 2 * tg;
        *(float2*)&p_s[rA * LP + c] = make_float2(sc[i][j][0], sc[i][j][1]);
        *(float2*)&p_s[(rA + 8) * LP + c] = make_float2(sc[i][j][2], sc[i][j][3]);
      }
    }
    __syncthreads();

    // ---- online softmax: 2 threads per row (32 cols each) ----
    {
      const int row = t >> 1, part = t & 1;
      float4* pr = (float4*)&p_s[row * LP + part * 32];
      float4 v0 = pr[0], v1 = pr[1], v2 = pr[2], v3 = pr[3];
      float4 v4 = pr[4], v5 = pr[5], v6 = pr[6], v7 = pr[7];
      float mt = fmaxf(fmaxf(fmaxf(v0.x, v0.y), fmaxf(v0.z, v0.w)),
                       fmaxf(fmaxf(v1.x, v1.y), fmaxf(v1.z, v1.w)));
      mt = fmaxf(mt, fmaxf(fmaxf(fmaxf(v2.x, v2.y), fmaxf(v2.z, v2.w)),
                           fmaxf(fmaxf(v3.x, v3.y), fmaxf(v3.z, v3.w))));
      mt = fmaxf(mt, fmaxf(fmaxf(fmaxf(v4.x, v4.y), fmaxf(v4.z, v4.w)),
                           fmaxf(fmaxf(v5.x, v5.y), fmaxf(v5.z, v5.w))));
      mt = fmaxf(mt, fmaxf(fmaxf(fmaxf(v6.x, v6.y), fmaxf(v6.z, v6.w)),
                           fmaxf(fmaxf(v7.x, v7.y), fmaxf(v7.z, v7.w))));
      mt = fmaxf(mt, __shfl_xor_sync(0xffffffffu, mt, 1));
      float m_old = m_s[row];
      float mn = fmaxf(m_old, mt);
      v0.x = __expf(v0.x - mn); v0.y = __expf(v0.y - mn);
      v0.z = __expf(v0.z - mn); v0.w = __expf(v0.w - mn);
      v1.x = __expf(v1.x - mn); v1.y = __expf(v1.y - mn);
      v1.z = __expf(v1.z - mn); v1.w = __expf(v1.w - mn);
      v2.x = __expf(v2.x - mn); v2.y = __expf(v2.y - mn);
      v2.z = __expf(v2.z - mn); v2.w = __expf(v2.w - mn);
      v3.x = __expf(v3.x - mn); v3.y = __expf(v3.y - mn);
      v3.z = __expf(v3.z - mn); v3.w = __expf(v3.w - mn);
      v4.x = __expf(v4.x - mn); v4.y = __expf(v4.y - mn);
      v4.z = __expf(v4.z - mn); v4.w = __expf(v4.w - mn);
      v5.x = __expf(v5.x - mn); v5.y = __expf(v5.y - mn);
      v5.z = __expf(v5.z - mn); v5.w = __expf(v5.w - mn);
      v6.x = __expf(v6.x - mn); v6.y = __expf(v6.y - mn);
      v6.z = __expf(v6.z - mn); v6.w = __expf(v6.w - mn);
      v7.x = __expf(v7.x - mn); v7.y = __expf(v7.y - mn);
      v7.z = __expf(v7.z - mn); v7.w = __expf(v7.w - mn);
      float s = (v0.x + v0.y + v0.z + v0.w) + (v1.x + v1.y + v1.z + v1.w) +
                (v2.x + v2.y + v2.z + v2.w) + (v3.x + v3.y + v3.z + v3.w) +
                (v4.x + v4.y + v4.z + v4.w) + (v5.x + v5.y + v5.z + v5.w) +
                (v6.x + v6.y + v6.z + v6.w) + (v7.x + v7.y + v7.z + v7.w);
      s += __shfl_xor_sync(0xffffffffu, s, 1);
      pr[0] = tf32x4(v0); pr[1] = tf32x4(v1);
      pr[2] = tf32x4(v2); pr[3] = tf32x4(v3);
      pr[4] = tf32x4(v4); pr[5] = tf32x4(v5);
      pr[6] = tf32x4(v6); pr[7] = tf32x4(v7);
      __syncwarp();
      if (part == 0) {
        float alpha = __expf(m_old - mn);
        m_s[row] = mn;
        alpha_s[row] = alpha;
        l_s[row] = l_s[row] * alpha + s;
      }
    }
    __syncthreads();

    // ---- rescale O ----
#pragma unroll
    for (int i = 0; i < 2; i++) {
      int rA = wr * 32 + i * 16 + g;
      float aA = alpha_s[rA], aB = alpha_s[rA + 8];
#pragma unroll
      for (int j = 0; j < 8; j++) {
        o[i][j][0] *= aA; o[i][j][1] *= aA;
        o[i][j][2] *= aB; o[i][j][3] *= aB;
      }
    }

    // ---- phase B: O += P V (128x128), warp tile 32x64 ----
    const uint32_t* ps = (const uint32_t*)p_s;
    const uint32_t* vs = (const uint32_t*)v_s;
#pragma unroll
    for (int kk = 0; kk < KTT; kk += 8) {
      uint32_t af[2][4], bf[8][2];
#pragma unroll
      for (int i = 0; i < 2; i++) {
        int r0 = wr * 32 + i * 16;
        af[i][0] = ps[(r0 + g) * LP + kk + tg];
        af[i][1] = ps[(r0 + g + 8) * LP + kk + tg];
        af[i][2] = ps[(r0 + g) * LP + kk + tg + 4];
        af[i][3] = ps[(r0 + g + 8) * LP + kk + tg + 4];
      }
#pragma unroll
      for (int j = 0; j < 8; j++) {
        int cb = wc * 64 + j * 8;
        bf[j][0] = vs[(kk + tg) * LV + cb + g];
        bf[j][1] = vs[(kk + tg + 4) * LV + cb + g];
      }
#pragma unroll
      for (int i = 0; i < 2; i++)
#pragma unroll
        for (int j = 0; j < 8; j++) mma_tf32(o[i][j], af[i], bf[j]);
    }
  }

  // ---- epilogue: normalize + residual ----
#pragma unroll
  for (int i = 0; i < 2; i++) {
    int rA = wr * 32 + i * 16 + g;
    int rB = rA + 8;
    float invA = 1.f / l_s[rA];
    float invB = 1.f / l_s[rB];
#pragma unroll
    for (int j = 0; j < 8; j++) {
      int c = wc * 64 + j * 8 + 2 * tg;
      size_t baseA = ((size_t)b * S_ + q0 + rA) * D_ + (size_t)h * E_ + c;
      size_t baseB = ((size_t)b * S_ + q0 + rB) * D_ + (size_t)h * E_ + c;
      float2 mA = *(const float2*)(modin + baseA);
      float2 mB = *(const float2*)(modin + baseB);
      float2 oA = make_float2(mA.x + o[i][j][0] * invA, mA.y + o[i][j][1] * invA);
      float2 oB = make_float2(mB.x + o[i][j][2] * invB, mB.y + o[i][j][3] * invB);
      *(float2*)(modout + baseA) = oA;
      *(float2*)(modout + baseB) = oB;
    }
  }
}

// ============================================================
extern "C" void kernel_launch(void* const* d_in, const int* in_sizes, int n_in,
                              void* d_out, int out_size) {
  const float* x     = (const float*)d_in[0];
  const float* W_in  = (const float*)d_in[1];
  const float* gamma = (const float*)d_in[2];
  const float* beta  = (const float*)d_in[3];
  const float* Wq    = (const float*)d_in[4];
  const float* Wk    = (const float*)d_in[5];
  const float* Wv    = (const float*)d_in[6];
  const float* Wf    = (const float*)d_in[7];
  const float* bf    = (const float*)d_in[8];
  float* out = (float*)d_out;

  float *mod, *h, *q, *k, *v, *mod2, *h2;
  cudaGetSymbolAddress((void**)&mod,  g_mod);
  cudaGetSymbolAddress((void**)&h,    g_h);
  cudaGetSymbolAddress((void**)&q,    g_q);
  cudaGetSymbolAddress((void**)&k,    g_k);
  cudaGetSymbolAddress((void**)&v,    g_v);
  cudaGetSymbolAddress((void**)&mod2, g_mod2);
  cudaGetSymbolAddress((void**)&h2,   g_h2);

  cudaFuncSetAttribute(k_attn, cudaFuncAttributeMaxDynamicSharedMemorySize, ATTN_SMEM);

  dim3 gdense(D_ / GBN, NT_ / GBM);     // (8, 64)
  k_gemm_dense<<<gdense, 256>>>(x, W_in, mod);

  k_ln<<<NT_, 256>>>(mod, h, gamma, beta);

  dim3 gqkv(S_ / GBM, B_ * H_, 3);      // (16, 32, 3)
  k_gemm_qkv<<<gqkv, 256>>>(h, Wq, Wk, Wv, q, k, v);

  dim3 gattn(S_ / QT, H_, B_);          // (16, 8, 4)
  k_attn<<<gattn, 256, ATTN_SMEM>>>(q, k, v, mod, mod2);

  k_ln<<<NT_, 256>>>(mod2, h2, gamma, beta);

  k_gemm_ffn<<<gdense, 256>>>(h2, Wf, bf, mod2, out);
}